// round 12
// baseline (speedup 1.0000x reference)
#include <cuda_runtime.h>
#include <cuda_fp16.h>

// Triline interpolation, fp16 SMEM tables + distance-2 software pipeline.
//   out[b, :] = lerp(x_line, cx) + lerp(y_line, cy) + lerp(z_line, cz)
// B = 1M, C = 64, N = 512.
//
// All three tables in SMEM as fp16 (192 KB, one CTA = all 64 channels).
// 8 lanes per point, 16B per lane per row: conflict-free LDS.128.
// 3-stage pipeline per iteration:
//   stage A (issue):   6 LDS gathers for point p (indices from 2 iters ago)
//   stage B (alu):     indices/weights for p+S from coords that arrived last iter
//   stage C (fetch):   coords LDG for p+2S  (LDG->use distance = 2 iterations)
//   stage D (consume): lerp + store for p

#define N_ROWS  512
#define C_CH    64
#define NCHUNK  148
#define BLOCK   1024
#define PTS_IT  (BLOCK / 8)                       // 128 points per CTA-iteration
#define TBL_HALVES (N_ROWS * C_CH)                // 32768 halves per table
#define SMEM_BYTES (3 * TBL_HALVES * 2)           // 192 KB

struct H8 { __half2 a, b, c, d; };

__device__ __forceinline__ H8 lds_h8(const __half* base, int halfOff) {
    uint4 u = *(const uint4*)(base + halfOff);
    H8 r;
    r.a = *(__half2*)&u.x;  r.b = *(__half2*)&u.y;
    r.c = *(__half2*)&u.z;  r.d = *(__half2*)&u.w;
    return r;
}

__global__ __launch_bounds__(BLOCK, 1) void triline_h16_kernel(
    const float* __restrict__ coords,   // [B, 3]
    const float* __restrict__ x_line,   // [N, C] fp32
    const float* __restrict__ y_line,
    const float* __restrict__ z_line,
    const float* __restrict__ grid,     // [N]
    float* __restrict__ out,            // [B, C] fp32
    int B, int ptsPer)
{
    extern __shared__ __half smh[];     // [3][512][64]
    __half* sx = smh;
    __half* sy = smh + TBL_HALVES;
    __half* sz = smh + 2 * TBL_HALVES;

    const int tIn = threadIdx.x;

    // ---- Stage all three tables, converting fp32 -> fp16 ----
    for (int i = tIn; i < TBL_HALVES / 4; i += BLOCK) {
        float4 vx = *(const float4*)(x_line + 4 * i);
        float4 vy = *(const float4*)(y_line + 4 * i);
        float4 vz = *(const float4*)(z_line + 4 * i);
        ((__half2*)sx)[2 * i]     = __floats2half2_rn(vx.x, vx.y);
        ((__half2*)sx)[2 * i + 1] = __floats2half2_rn(vx.z, vx.w);
        ((__half2*)sy)[2 * i]     = __floats2half2_rn(vy.x, vy.y);
        ((__half2*)sy)[2 * i + 1] = __floats2half2_rn(vy.z, vy.w);
        ((__half2*)sz)[2 * i]     = __floats2half2_rn(vz.x, vz.y);
        ((__half2*)sz)[2 * i + 1] = __floats2half2_rn(vz.z, vz.w);
    }

    const float g0    = __ldg(grid);
    const float invdx = 1.0f / (__ldg(grid + 1) - g0);

    __syncthreads();

    const int hoff   = (tIn & 7) << 3;           // half-channel offset (8 per lane)
    const int pstart = blockIdx.x * ptsPer;
    const int pend   = min(pstart + ptsPer, B);

    int p = pstart + (tIn >> 3);
    if (p >= pend) return;

    // Clamped addresses for pipeline lookahead (tail-safe: recompute garbage,
    // but never read OOB and never store from lookahead stages).
    const int pmax = pend - 1;

    // ---- Prologue ----
    // Stage state:
    //   idx/w      : ready-to-gather indices for current p
    //   qx,qy,qz   : raw positions for p+S (index math pending)
    //   rx,ry,rz   : raw coords for p+2S (position math pending)
    int ix, iy, iz;  float wx, wy, wz;
    {
        const float cx = __ldg(coords + 3 * p + 0);
        const float cy = __ldg(coords + 3 * p + 1);
        const float cz = __ldg(coords + 3 * p + 2);
        const float px = (cx - g0) * invdx;
        const float py = (cy - g0) * invdx;
        const float pz = (cz - g0) * invdx;
        ix = min(max(__float2int_rd(px), 0), N_ROWS - 2);
        iy = min(max(__float2int_rd(py), 0), N_ROWS - 2);
        iz = min(max(__float2int_rd(pz), 0), N_ROWS - 2);
        wx = px - (float)ix;  wy = py - (float)iy;  wz = pz - (float)iz;
    }
    float qx, qy, qz;
    {
        const int p1 = min(p + PTS_IT, pmax);
        qx = (__ldg(coords + 3 * p1 + 0) - g0) * invdx;
        qy = (__ldg(coords + 3 * p1 + 1) - g0) * invdx;
        qz = (__ldg(coords + 3 * p1 + 2) - g0) * invdx;
    }
    float rx, ry, rz;
    {
        const int p2 = min(p + 2 * PTS_IT, pmax);
        rx = __ldg(coords + 3 * p2 + 0);
        ry = __ldg(coords + 3 * p2 + 1);
        rz = __ldg(coords + 3 * p2 + 2);
    }

    for (; p < pend; ) {
        // ---- Stage A: issue this point's 6 gathers (addresses ready) ----
        const H8 X0 = lds_h8(sx, (ix << 6) + hoff);
        const H8 X1 = lds_h8(sx, ((ix + 1) << 6) + hoff);
        const H8 Y0 = lds_h8(sy, (iy << 6) + hoff);
        const H8 Y1 = lds_h8(sy, ((iy + 1) << 6) + hoff);
        const H8 Z0 = lds_h8(sz, (iz << 6) + hoff);
        const H8 Z1 = lds_h8(sz, ((iz + 1) << 6) + hoff);

        const __half2 wx2 = __float2half2_rn(wx);
        const __half2 wy2 = __float2half2_rn(wy);
        const __half2 wz2 = __float2half2_rn(wz);

        // ---- Stage B: index/weight math for p+S (ALU only, fills LDS shadow) ----
        const int nix = min(max(__float2int_rd(qx), 0), N_ROWS - 2);
        const int niy = min(max(__float2int_rd(qy), 0), N_ROWS - 2);
        const int niz = min(max(__float2int_rd(qz), 0), N_ROWS - 2);
        const float nwx = qx - (float)nix;
        const float nwy = qy - (float)niy;
        const float nwz = qz - (float)niz;

        // ---- Stage B': positions for p+2S from coords that arrived last iter ----
        const float nqx = (rx - g0) * invdx;
        const float nqy = (ry - g0) * invdx;
        const float nqz = (rz - g0) * invdx;

        // ---- Stage C: coords LDG for p+3S (use distance = 2 iterations) ----
        const int pf = min(p + 3 * PTS_IT, pmax);
        const float nrx = __ldg(coords + 3 * pf + 0);
        const float nry = __ldg(coords + 3 * pf + 1);
        const float nrz = __ldg(coords + 3 * pf + 2);

        // ---- Stage D: consume gathers, lerp, store ----
        __half2 lxa = __hfma2(wx2, __hsub2(X1.a, X0.a), X0.a);
        __half2 lxb = __hfma2(wx2, __hsub2(X1.b, X0.b), X0.b);
        __half2 lxc = __hfma2(wx2, __hsub2(X1.c, X0.c), X0.c);
        __half2 lxd = __hfma2(wx2, __hsub2(X1.d, X0.d), X0.d);
        __half2 lya = __hfma2(wy2, __hsub2(Y1.a, Y0.a), Y0.a);
        __half2 lyb = __hfma2(wy2, __hsub2(Y1.b, Y0.b), Y0.b);
        __half2 lyc = __hfma2(wy2, __hsub2(Y1.c, Y0.c), Y0.c);
        __half2 lyd = __hfma2(wy2, __hsub2(Y1.d, Y0.d), Y0.d);
        __half2 lza = __hfma2(wz2, __hsub2(Z1.a, Z0.a), Z0.a);
        __half2 lzb = __hfma2(wz2, __hsub2(Z1.b, Z0.b), Z0.b);
        __half2 lzc = __hfma2(wz2, __hsub2(Z1.c, Z0.c), Z0.c);
        __half2 lzd = __hfma2(wz2, __hsub2(Z1.d, Z0.d), Z0.d);

        const float2 fa = __half22float2(lxa), ga = __half22float2(lya), ha = __half22float2(lza);
        const float2 fb = __half22float2(lxb), gb = __half22float2(lyb), hb = __half22float2(lzb);
        const float2 fc = __half22float2(lxc), gc = __half22float2(lyc), hc = __half22float2(lzc);
        const float2 fd = __half22float2(lxd), gd = __half22float2(lyd), hd = __half22float2(lzd);

        float4 r0, r1;
        r0.x = fa.x + ga.x + ha.x;  r0.y = fa.y + ga.y + ha.y;
        r0.z = fb.x + gb.x + hb.x;  r0.w = fb.y + gb.y + hb.y;
        r1.x = fc.x + gc.x + hc.x;  r1.y = fc.y + gc.y + hc.y;
        r1.z = fd.x + gd.x + hd.x;  r1.w = fd.y + gd.y + hd.y;

        float* o = out + (size_t)p * C_CH + hoff;
        *(float4*)o       = r0;
        *(float4*)(o + 4) = r1;

        // ---- Rotate pipeline state ----
        p += PTS_IT;
        ix = nix; iy = niy; iz = niz;
        wx = nwx; wy = nwy; wz = nwz;
        qx = nqx; qy = nqy; qz = nqz;
        rx = nrx; ry = nry; rz = nrz;
    }
}

extern "C" void kernel_launch(void* const* d_in, const int* in_sizes, int n_in,
                              void* d_out, int out_size)
{
    const float* coords = (const float*)d_in[0];
    const float* x_line = (const float*)d_in[1];
    const float* y_line = (const float*)d_in[2];
    const float* z_line = (const float*)d_in[3];
    const float* grid   = (const float*)d_in[4];
    float* out = (float*)d_out;

    const int B = in_sizes[0] / 3;                 // 1048576
    const int ptsPer = (B + NCHUNK - 1) / NCHUNK;  // 7086

    static int smem_set = 0;
    if (!smem_set) {
        cudaFuncSetAttribute(triline_h16_kernel,
                             cudaFuncAttributeMaxDynamicSharedMemorySize, SMEM_BYTES);
        smem_set = 1;
    }

    triline_h16_kernel<<<NCHUNK, BLOCK, SMEM_BYTES>>>(
        coords, x_line, y_line, z_line, grid, out, B, ptsPer);
}